// round 3
// baseline (speedup 1.0000x reference)
#include <cuda_runtime.h>
#include <stdint.h>

// GazeOnce360 post-processing, round 3:
//   K1 scan: prefilter + exact softmax score; candidates keyed & scattered into
//            per-bin buckets (hist atomicAdd returns the slot) — single pass.
//   K2 finish: suffix-scan hist -> cutoff bin B -> gather bins>=B -> bitonic
//              top-512 sort -> decode boxes.
//   K3 mask: 512x512 IoU suppression bitmask.
//   K4 nms:  ffs-skip greedy scan + output; re-zeroes hist for next launch.
//
// Inputs: loc [1,N,4] f32, conf [1,N,2] f32, priors [N,4] f32. N=2,097,152.
// Output: [512,5] f32.

#define KDET 512
#define NBINS 8192
#define BIN_BASE (0x3F666667u >> 8)   // bits of smallest float > 0.9f, >>8
#define SLOTS 128                     // per-bin bucket capacity (expect ~30 max)
#define CAND_CAP 1024

// -------- scratch (static device arrays; zero-initialized at module load) ----
__device__ unsigned int       g_hist[NBINS];          // doubles as slot counters
__device__ unsigned long long g_bins[NBINS * SLOTS];  // 8MB bucket store
__device__ float4             g_cand[KDET];
__device__ float              g_score[KDET];
__device__ unsigned int       g_mask[KDET * 16];

// ---------------- K1: fused scan -> per-bin buckets ----------------
// 8 float4 loads (16 conf pairs) per thread for MLP. For candidates c1 > c0 so
// softmax(c0,c1)[1] == 1/(exp(c0-c1)+1) exactly (max-subtracted form, e1 = 1).
// Prefilter d > 2.19 (< ln 9, sigmoid(2.19)=0.8993) skips expf for ~94% lanes.
__global__ void __launch_bounds__(512) k_scan(const float4* __restrict__ conf4,
                                              int nPairs) {
    int base = blockIdx.x * (512 * 8) + threadIdx.x;
    float4 f[8];
#pragma unroll
    for (int k = 0; k < 8; k++) {
        int idx = base + k * 512;
        f[k] = (idx < nPairs) ? conf4[idx] : make_float4(0.f, 0.f, 0.f, 0.f);
    }
#pragma unroll
    for (int k = 0; k < 8; k++) {
        int pidx = base + k * 512;
#pragma unroll
        for (int q = 0; q < 2; q++) {
            float c0 = q ? f[k].z : f[k].x;
            float c1 = q ? f[k].w : f[k].y;
            if (c1 - c0 > 2.19f && pidx < nPairs) {
                float e0 = expf(c0 - c1);
                float s  = 1.0f / (e0 + 1.0f);
                if (s > 0.9f) {
                    unsigned bits = __float_as_uint(s);
                    unsigned bin  = (bits >> 8) - BIN_BASE;
                    unsigned slot = atomicAdd(&g_hist[bin], 1u);
                    if (slot < SLOTS) {
                        unsigned ei = 2u * (unsigned)pidx + (unsigned)q;
                        g_bins[bin * SLOTS + slot] =
                            ((unsigned long long)bits << 32)
                          | (unsigned long long)(0xFFFFFFFFu - ei);
                    }
                }
            }
        }
    }
}

// ---------------- K2: select cutoff + gather + sort + decode ----------------
__global__ void __launch_bounds__(512) k_finish(const float4* __restrict__ loc4,
                                                const float4* __restrict__ pri4) {
    __shared__ unsigned ssum[512];
    __shared__ unsigned sB, sn;
    __shared__ unsigned long long sk[CAND_CAP];
    int t = threadIdx.x;
    if (t == 0) { sB = 0u; sn = 0u; }
    sk[t] = 0ULL; sk[t + 512] = 0ULL;

    // suffix-sum of histogram; B = max bin with suffix-count >= 512 (else 0)
    unsigned h[16];
    unsigned psum = 0;
#pragma unroll
    for (int j = 0; j < 16; j++) { h[j] = g_hist[t * 16 + j]; psum += h[j]; }
    ssum[t] = psum;
    __syncthreads();
    for (int off = 1; off < 512; off <<= 1) {
        unsigned v = (t + off < 512) ? ssum[t + off] : 0u;
        __syncthreads();
        ssum[t] += v;
        __syncthreads();
    }
    unsigned cum = (t < 511) ? ssum[t + 1] : 0u;   // sum of bins >= 16(t+1)
    int best = -1;
#pragma unroll
    for (int j = 15; j >= 0; j--) {
        cum += h[j];                                // sum of bins >= 16t+j
        if (cum >= KDET) { best = t * 16 + j; break; }
    }
    if (best >= 0) atomicMax(&sB, (unsigned)best);
    __syncthreads();

    // gather all keys of bins >= B into smem (order arbitrary; sort fixes it)
    unsigned B = sB;
#pragma unroll
    for (int j = 0; j < 16; j++) {
        unsigned b = (unsigned)t * 16 + (unsigned)j;
        if (b >= B && h[j] > 0) {
            unsigned cnt  = min(h[j], (unsigned)SLOTS);
            unsigned base = atomicAdd(&sn, cnt);
            for (unsigned k = 0; k < cnt; k++) {
                unsigned p = base + k;
                if (p < CAND_CAP) sk[p] = g_bins[b * SLOTS + k];
            }
        }
    }
    __syncthreads();

    // bitonic sort 1024 keys descending
    for (int k = 2; k <= CAND_CAP; k <<= 1) {
        for (int j = k >> 1; j > 0; j >>= 1) {
#pragma unroll
            for (int r = 0; r < 2; r++) {
                int i = t + r * 512;
                int ixj = i ^ j;
                if (ixj > i) {
                    unsigned long long a = sk[i], bb = sk[ixj];
                    bool desc = ((i & k) == 0);
                    if (desc ? (a < bb) : (a > bb)) { sk[i] = bb; sk[ixj] = a; }
                }
            }
            __syncthreads();
        }
    }

    // decode top 512
    {
        unsigned long long key = sk[t];
        unsigned sb = (unsigned)(key >> 32);
        float4 c = make_float4(0.f, 0.f, 0.f, 0.f);
        float sc = 0.f;
        if (sb) {
            unsigned idx = 0xFFFFFFFFu - (unsigned)(key & 0xFFFFFFFFull);
            float4 l = loc4[idx];
            float4 p = pri4[idx];
            float cx = p.x + (l.x * 0.1f) * p.z;
            float cy = p.y + (l.y * 0.1f) * p.w;
            float w  = p.z * expf(l.z * 0.2f);
            float hh = p.w * expf(l.w * 0.2f);
            float x1 = cx - w * 0.5f;
            float y1 = cy - hh * 0.5f;
            float x2 = x1 + w;
            float y2 = y1 + hh;
            c = make_float4(x1 * 2048.f, y1 * 2048.f, x2 * 2048.f, y2 * 2048.f);
            sc = __uint_as_float(sb);
        }
        g_cand[t]  = c;
        g_score[t] = sc;
    }
}

// ---------------- K3: 512x512 suppression bitmask -----------------
__global__ void __launch_bounds__(256) k_mask() {
    int w = blockIdx.x * blockDim.x + threadIdx.x;     // 0..8191
    int i = w >> 4, c = w & 15;
    float4 bi = g_cand[i];
    float areai = (bi.z - bi.x + 1.f) * (bi.w - bi.y + 1.f);
    unsigned bits = 0u;
#pragma unroll 4
    for (int b = 0; b < 32; b++) {
        int j = c * 32 + b;
        float4 bj = g_cand[j];
        float areaj = (bj.z - bj.x + 1.f) * (bj.w - bj.y + 1.f);
        float xx1 = fmaxf(bi.x, bj.x), yy1 = fmaxf(bi.y, bj.y);
        float xx2 = fminf(bi.z, bj.z), yy2 = fminf(bi.w, bj.w);
        float ww = fmaxf(xx2 - xx1 + 1.f, 0.f);
        float hh = fmaxf(yy2 - yy1 + 1.f, 0.f);
        float inter = ww * hh;
        float iou = inter / (areai + areaj - inter);
        if (iou > 0.4f && j > i) bits |= (1u << b);
    }
    g_mask[w] = bits;
}

// ---------------- K4: ffs-skip greedy NMS + output; re-zero hist ----------
__global__ void __launch_bounds__(512) k_nms_out(float* __restrict__ out) {
    __shared__ uint4 smask[KDET * 4];
    __shared__ unsigned skeep[16];
    int t = threadIdx.x;

    // restore scratch invariant for the next launch (hist == 0)
    {
        uint4* hz = (uint4*)g_hist;
#pragma unroll
        for (int i = 0; i < 4; i++)
            hz[t + i * 512] = make_uint4(0u, 0u, 0u, 0u);
    }

    for (int i = t; i < KDET * 4; i += 512)
        smask[i] = ((const uint4*)g_mask)[i];

    bool k0 = g_score[t] > 0.0f;                       // keep0 = top_s > 0
    unsigned wball = __ballot_sync(0xFFFFFFFFu, k0);
    if ((t & 31) == 0) skeep[t >> 5] = wball;
    __syncthreads();

    if (t == 0) {
        unsigned kw[16];
#pragma unroll
        for (int w = 0; w < 16; w++) kw[w] = skeep[w];
#pragma unroll
        for (int w = 0; w < 16; w++) {
            unsigned cur = kw[w];
            while (cur) {
                int bit = __ffs(cur) - 1;
                int i = w * 32 + bit;
                cur &= cur - 1;
                const uint4* mr = &smask[i * 4];
                uint4 m0 = mr[0], m1 = mr[1], m2 = mr[2], m3 = mr[3];
                kw[0]  &= ~m0.x; kw[1]  &= ~m0.y; kw[2]  &= ~m0.z; kw[3]  &= ~m0.w;
                kw[4]  &= ~m1.x; kw[5]  &= ~m1.y; kw[6]  &= ~m1.z; kw[7]  &= ~m1.w;
                kw[8]  &= ~m2.x; kw[9]  &= ~m2.y; kw[10] &= ~m2.z; kw[11] &= ~m2.w;
                kw[12] &= ~m3.x; kw[13] &= ~m3.y; kw[14] &= ~m3.z; kw[15] &= ~m3.w;
                cur &= kw[w];
            }
        }
#pragma unroll
        for (int w = 0; w < 16; w++) skeep[w] = kw[w];
    }
    __syncthreads();

    unsigned kept = (skeep[t >> 5] >> (t & 31)) & 1u;
    float4 c = g_cand[t];
    float sc = g_score[t];
    const float inv = 1.0f / 2048.0f;
    float o0 = 0.f, o1 = 0.f, o2 = 0.f, o3 = 0.f, o4 = 0.f;
    if (kept) { o0 = c.x * inv; o1 = c.y * inv; o2 = c.z * inv; o3 = c.w * inv; o4 = sc; }
    out[t * 5 + 0] = o0;
    out[t * 5 + 1] = o1;
    out[t * 5 + 2] = o2;
    out[t * 5 + 3] = o3;
    out[t * 5 + 4] = o4;
}

extern "C" void kernel_launch(void* const* d_in, const int* in_sizes, int n_in,
                              void* d_out, int out_size) {
    const float4* loc4  = (const float4*)d_in[0];
    const float4* conf4 = (const float4*)d_in[1];
    const float4* pri4  = (const float4*)d_in[2];
    float* out = (float*)d_out;

    int nElem  = in_sizes[1] / 2;                   // N priors
    int nPairs = (nElem + 1) / 2;                   // float4 count of conf
    int scanBlocks = (nPairs + 4095) / 4096;        // 8 float4 per thread

    k_scan<<<scanBlocks, 512>>>(conf4, nPairs);
    k_finish<<<1, 512>>>(loc4, pri4);
    k_mask<<<(KDET * 16) / 256, 256>>>();
    k_nms_out<<<1, 512>>>(out);
}

// round 4
// speedup vs baseline: 1.5225x; 1.5225x over previous
#include <cuda_runtime.h>
#include <stdint.h>

// GazeOnce360 post-processing, round 4:
//   K1 scan:   prefilter + exact softmax score -> per-bin buckets (single pass).
//   K2 finish: suffix-scan hist -> cutoff B -> atomic-free parallel gather via
//              computed per-bin ranks -> bitonic top-512 sort -> decode.
//   K3 mask:   512x512 IoU suppression bitmask.
//   K4 nms:    word-at-a-time warp greedy NMS (register intra-word resolve),
//              output write, hist re-zero.

#define KDET 512
#define NBINS 8192
#define BIN_BASE (0x3F666667u >> 8)   // bits of smallest float > 0.9f, >>8
#define SLOTS 128                     // per-bin capacity (expected max ~60)
#define CAND_CAP 1024
#define WLCAP 768

__device__ unsigned int       g_hist[NBINS];          // slot counters (==hist)
__device__ unsigned long long g_bins[NBINS * SLOTS];  // bucket store
__device__ float4             g_cand[KDET];
__device__ float              g_score[KDET];
__device__ unsigned int       g_mask[KDET * 16];

// ---------------- K1: fused scan -> per-bin buckets ----------------
// softmax(c0,c1)[1] == 1/(exp(c0-c1)+1) exactly when c1>c0 (max-subtracted, e1=1).
// Prefilter d>2.19 (< ln9; sigmoid(2.19)=0.8993) skips expf for ~94% of lanes.
__global__ void __launch_bounds__(512) k_scan(const float4* __restrict__ conf4,
                                              int nPairs) {
    int base = blockIdx.x * (512 * 8) + threadIdx.x;
    float4 f[8];
#pragma unroll
    for (int k = 0; k < 8; k++) {
        int idx = base + k * 512;
        f[k] = (idx < nPairs) ? conf4[idx] : make_float4(0.f, 0.f, 0.f, 0.f);
    }
#pragma unroll
    for (int k = 0; k < 8; k++) {
        int pidx = base + k * 512;
#pragma unroll
        for (int q = 0; q < 2; q++) {
            float c0 = q ? f[k].z : f[k].x;
            float c1 = q ? f[k].w : f[k].y;
            if (c1 - c0 > 2.19f && pidx < nPairs) {
                float e0 = expf(c0 - c1);
                float s  = 1.0f / (e0 + 1.0f);
                if (s > 0.9f) {
                    unsigned bits = __float_as_uint(s);
                    unsigned bin  = (bits >> 8) - BIN_BASE;
                    unsigned slot = atomicAdd(&g_hist[bin], 1u);
                    if (slot < SLOTS) {
                        unsigned ei = 2u * (unsigned)pidx + (unsigned)q;
                        g_bins[bin * SLOTS + slot] =
                            ((unsigned long long)bits << 32)
                          | (unsigned long long)(0xFFFFFFFFu - ei);
                    }
                }
            }
        }
    }
}

// ---------------- K2: select + parallel gather + sort + decode ----------------
__global__ void __launch_bounds__(512) k_finish(const float4* __restrict__ loc4,
                                                const float4* __restrict__ pri4) {
    __shared__ unsigned ssum[512];
    __shared__ unsigned sB, snw;
    __shared__ unsigned wbin[WLCAP], wbase[WLCAP], wcnt[WLCAP];
    __shared__ unsigned long long sk[CAND_CAP];
    int t = threadIdx.x;
    if (t == 0) { sB = 0u; snw = 0u; }
    sk[t] = 0ULL; sk[t + 512] = 0ULL;

    // per-thread bins 16t..16t+15; suffix sums at 16-bin granularity
    unsigned h[16];
    unsigned psum = 0;
#pragma unroll
    for (int j = 0; j < 16; j++) { h[j] = g_hist[t * 16 + j]; psum += h[j]; }
    ssum[t] = psum;
    __syncthreads();
    for (int off = 1; off < 512; off <<= 1) {
        unsigned v = (t + off < 512) ? ssum[t + off] : 0u;
        __syncthreads();
        ssum[t] += v;
        __syncthreads();
    }

    // B = max bin with suffix-count >= 512 (else 0)
    {
        unsigned cum = (t < 511) ? ssum[t + 1] : 0u;
        int best = -1;
#pragma unroll
        for (int j = 15; j >= 0; j--) {
            cum += h[j];
            if (cum >= KDET) { best = t * 16 + j; break; }
        }
        if (best >= 0) atomicMax(&sB, (unsigned)best);
    }
    __syncthreads();
    unsigned B = sB;

    // worklist of active bins >= B with exact output rank (no global atomics):
    // base(bin) = count of keys in strictly higher bins (descending-score order)
    {
        unsigned suf = (t < 511) ? ssum[t + 1] : 0u;
#pragma unroll
        for (int j = 15; j >= 0; j--) {
            unsigned b = (unsigned)t * 16 + (unsigned)j;
            if (b >= B && h[j] > 0 && suf < CAND_CAP) {
                unsigned e = atomicAdd(&snw, 1u);       // smem, ~40 total
                if (e < WLCAP) {
                    wbin[e] = b; wbase[e] = suf; wcnt[e] = min(h[j], (unsigned)SLOTS);
                }
            }
            suf += h[j];
        }
    }
    __syncthreads();

    // warp-cooperative copy: each entry handled by one warp, lanes split slots
    {
        int wid = t >> 5, lane = t & 31;
        unsigned nw = min(snw, (unsigned)WLCAP);
        for (unsigned e = wid; e < nw; e += 16) {
            unsigned bin = wbin[e], bs = wbase[e], cn = wcnt[e];
            for (unsigned k = lane; k < cn; k += 32) {
                unsigned p = bs + k;
                if (p < CAND_CAP) sk[p] = g_bins[bin * SLOTS + k];
            }
        }
    }
    __syncthreads();

    // bitonic sort 1024 keys descending
    for (int k = 2; k <= CAND_CAP; k <<= 1) {
        for (int j = k >> 1; j > 0; j >>= 1) {
#pragma unroll
            for (int r = 0; r < 2; r++) {
                int i = t + r * 512;
                int ixj = i ^ j;
                if (ixj > i) {
                    unsigned long long a = sk[i], bb = sk[ixj];
                    bool desc = ((i & k) == 0);
                    if (desc ? (a < bb) : (a > bb)) { sk[i] = bb; sk[ixj] = a; }
                }
            }
            __syncthreads();
        }
    }

    // decode top 512
    {
        unsigned long long key = sk[t];
        unsigned sb = (unsigned)(key >> 32);
        float4 c = make_float4(0.f, 0.f, 0.f, 0.f);
        float sc = 0.f;
        if (sb) {
            unsigned idx = 0xFFFFFFFFu - (unsigned)(key & 0xFFFFFFFFull);
            float4 l = loc4[idx];
            float4 p = pri4[idx];
            float cx = p.x + (l.x * 0.1f) * p.z;
            float cy = p.y + (l.y * 0.1f) * p.w;
            float w  = p.z * expf(l.z * 0.2f);
            float hh = p.w * expf(l.w * 0.2f);
            float x1 = cx - w * 0.5f;
            float y1 = cy - hh * 0.5f;
            float x2 = x1 + w;
            float y2 = y1 + hh;
            c = make_float4(x1 * 2048.f, y1 * 2048.f, x2 * 2048.f, y2 * 2048.f);
            sc = __uint_as_float(sb);
        }
        g_cand[t]  = c;
        g_score[t] = sc;
    }
}

// ---------------- K3: 512x512 suppression bitmask -----------------
__global__ void __launch_bounds__(256) k_mask() {
    int w = blockIdx.x * blockDim.x + threadIdx.x;     // 0..8191
    int i = w >> 4, c = w & 15;
    float4 bi = g_cand[i];
    float areai = (bi.z - bi.x + 1.f) * (bi.w - bi.y + 1.f);
    unsigned bits = 0u;
#pragma unroll 4
    for (int b = 0; b < 32; b++) {
        int j = c * 32 + b;
        float4 bj = g_cand[j];
        float areaj = (bj.z - bj.x + 1.f) * (bj.w - bj.y + 1.f);
        float xx1 = fmaxf(bi.x, bj.x), yy1 = fmaxf(bi.y, bj.y);
        float xx2 = fminf(bi.z, bj.z), yy2 = fminf(bi.w, bj.w);
        float ww = fmaxf(xx2 - xx1 + 1.f, 0.f);
        float hh = fmaxf(yy2 - yy1 + 1.f, 0.f);
        float inter = ww * hh;
        float iou = inter / (areai + areaj - inter);
        if (iou > 0.4f && j > i) bits |= (1u << b);
    }
    g_mask[w] = bits;
}

// ---------------- K4: word-at-a-time warp NMS + output; re-zero hist ----------
__global__ void __launch_bounds__(512) k_nms_out(float* __restrict__ out) {
    __shared__ unsigned smask[KDET * 16];              // 8KB
    __shared__ unsigned skeep[16];
    int t = threadIdx.x;

    // restore scratch invariant for next launch
    {
        uint4* hz = (uint4*)g_hist;
#pragma unroll
        for (int i = 0; i < 4; i++)
            hz[t + i * 512] = make_uint4(0u, 0u, 0u, 0u);
    }
    for (int i = t; i < KDET * 4; i += 512)
        ((uint4*)smask)[i] = ((const uint4*)g_mask)[i];

    bool k0 = g_score[t] > 0.0f;                       // keep0 = top_s > 0
    unsigned wball = __ballot_sync(0xFFFFFFFFu, k0);
    if ((t & 31) == 0) skeep[t >> 5] = wball;
    __syncthreads();

    if (t < 32) {
        unsigned L = (unsigned)t & 15u;                // lanes 16-31 mirror 0-15
        unsigned kw = skeep[L];
        // preload this word's intra-mask column (static indexing -> registers)
        unsigned mi[32];
#pragma unroll
        for (int j = 0; j < 32; j++)
            mi[j] = smask[(32u * L + j) * 16u + L];

        for (int w = 0; w < 16; w++) {
            // speculative intra-word greedy resolve (only lane w's result used)
            unsigned cur = kw;
#pragma unroll
            for (int j = 0; j < 32; j++) {
                unsigned tm = (unsigned)(((int)(cur << (31 - j))) >> 31);
                cur &= ~(mi[j] & tm);
            }
            unsigned acc = __shfl_sync(0xFFFFFFFFu, cur, w);
            if ((int)L == w) kw = cur;                 // word w final
            // apply accepted rows' masks to own word (uniform loop, no divergence)
            unsigned a = acc;
            while (a) {
                int b = __ffs(a) - 1;
                a &= a - 1;
                kw &= ~smask[(32u * w + b) * 16u + L];
            }
        }
        if (t < 16) skeep[L] = kw;
    }
    __syncthreads();

    unsigned kept = (skeep[t >> 5] >> (t & 31)) & 1u;
    float4 c = g_cand[t];
    float sc = g_score[t];
    const float inv = 1.0f / 2048.0f;
    float o0 = 0.f, o1 = 0.f, o2 = 0.f, o3 = 0.f, o4 = 0.f;
    if (kept) { o0 = c.x * inv; o1 = c.y * inv; o2 = c.z * inv; o3 = c.w * inv; o4 = sc; }
    out[t * 5 + 0] = o0;
    out[t * 5 + 1] = o1;
    out[t * 5 + 2] = o2;
    out[t * 5 + 3] = o3;
    out[t * 5 + 4] = o4;
}

extern "C" void kernel_launch(void* const* d_in, const int* in_sizes, int n_in,
                              void* d_out, int out_size) {
    const float4* loc4  = (const float4*)d_in[0];
    const float4* conf4 = (const float4*)d_in[1];
    const float4* pri4  = (const float4*)d_in[2];
    float* out = (float*)d_out;

    int nElem  = in_sizes[1] / 2;                   // N priors
    int nPairs = (nElem + 1) / 2;                   // float4 count of conf
    int scanBlocks = (nPairs + 4095) / 4096;        // 8 float4 per thread

    k_scan<<<scanBlocks, 512>>>(conf4, nPairs);
    k_finish<<<1, 512>>>(loc4, pri4);
    k_mask<<<(KDET * 16) / 256, 256>>>();
    k_nms_out<<<1, 512>>>(out);
}